// round 14
// baseline (speedup 1.0000x reference)
#include <cuda_runtime.h>
#include <stdint.h>

#define N_TOK (16 * 8192)   // 131072 tokens
#define NCOL 128            // C
#define GROUPS 32           // 4 segments per group
#define SPL 32              // token splits per group
#define THREADS 256
#define WARPS 8
#define TOK_PER_BLOCK (N_TOK / SPL)           // 4096
#define TOK_PER_WARP (TOK_PER_BLOCK / WARPS)  // 512
#define KITERS (TOK_PER_WARP / 128)           // 4
#define EVCAP 1024          // event-list capacity (mean 64, 121 sigma margin)
#define DP 3                // cp.async ring depth in PAIRS (6 rows in flight)

// Device scratch (no allocations allowed)
__device__ double        g_s[NCOL * NCOL];   // per-segment prob sums s[c][j]
__device__ double        g_ssq[NCOL];        // per-segment sum ||p||^2
__device__ int           g_cnt[NCOL];        // per-segment valid count n
__device__ unsigned char g_keys[N_TOK];      // packed: valid ? seg : 0xFF
__device__ int           g_done;             // accum block-completion ticket

// ---------------------------------------------------------------------------
// Kernel 1: zero accumulators + pack keys. 4 tokens/thread, vectorized.
// Mask dtype detected per block from nonzero-byte pattern of first 4096 bytes.
// ---------------------------------------------------------------------------
__global__ void __launch_bounds__(THREADS)
init_pack_kernel(const int* __restrict__ assign, const void* __restrict__ mask) {
    const int t = threadIdx.x;

    // --- inline mode detect (atomic-free, L2-hit broadcast) ---
    const uchar4* mb = (const uchar4*)mask;
    unsigned f = 0;
    #pragma unroll
    for (int k = 0; k < 4; ++k) {           // 256 thr * 4 uchar4 = 4096 bytes
        uchar4 u = mb[t * 4 + k];
        f |= (u.x ? 1u : 0u) | (u.y ? 2u : 0u) | (u.z ? 4u : 0u) | (u.w ? 8u : 0u);
    }
    f = __reduce_or_sync(0xFFFFFFFFu, f);
    __shared__ unsigned sf[WARPS];
    if ((t & 31) == 0) sf[t >> 5] = f;
    __syncthreads();
    unsigned fr = 0;
    #pragma unroll
    for (int w = 0; w < WARPS; ++w) fr |= sf[w];
    int mode;                                // 1=int32, 2=float32, 0=uint8
    if ((fr & 0xEu) == 0)      mode = 1;
    else if ((fr & 0x3u) == 0) mode = 2;
    else                       mode = 0;

    // --- pack 4 tokens + zero accumulators ---
    const int gid = blockIdx.x * blockDim.x + t;   // token-group id (4 tokens)
    const int i0  = gid * 4;
    if (i0 < N_TOK) {
        const int4 a4 = __ldg((const int4*)assign + gid);
        int v0, v1, v2, v3;
        if (mode == 1) {
            const int4 m4 = __ldg((const int4*)mask + gid);
            v0 = m4.x != 0; v1 = m4.y != 0; v2 = m4.z != 0; v3 = m4.w != 0;
        } else if (mode == 2) {
            const float4 m4 = __ldg((const float4*)mask + gid);
            v0 = m4.x != 0.f; v1 = m4.y != 0.f; v2 = m4.z != 0.f; v3 = m4.w != 0.f;
        } else {
            const uchar4 m4 = ((const uchar4*)mask)[gid];
            v0 = m4.x != 0; v1 = m4.y != 0; v2 = m4.z != 0; v3 = m4.w != 0;
        }
        uchar4 k4;
        k4.x = v0 ? (unsigned char)a4.x : (unsigned char)0xFF;
        k4.y = v1 ? (unsigned char)a4.y : (unsigned char)0xFF;
        k4.z = v2 ? (unsigned char)a4.z : (unsigned char)0xFF;
        k4.w = v3 ? (unsigned char)a4.w : (unsigned char)0xFF;
        ((uchar4*)g_keys)[gid] = k4;
    }
    if (i0 < NCOL * NCOL) {
        g_s[i0] = 0.0; g_s[i0 + 1] = 0.0; g_s[i0 + 2] = 0.0; g_s[i0 + 3] = 0.0;
    }
    if (i0 < NCOL) {
        #pragma unroll
        for (int k = 0; k < 4; ++k) { g_ssq[i0 + k] = 0.0; g_cnt[i0 + k] = 0; }
    }
    if (gid == 0) g_done = 0;
}

// ---------------------------------------------------------------------------
// Kernel 2: accumulation + fused finalize. grid = (SPL, GROUPS).
// Phase A: all warps compact matching tokens into ONE block-level event list.
// Phase B: warp w takes events w, w+8, ...; rows staged via cp.async into a
//          per-warp smem ring (DP pair-groups deep -> 2*DP rows in flight with
//          ZERO register cost; R9 showed register prefetch kills occupancy).
//          Constant-pending protocol: every iteration commits exactly one
//          group (empty past the end) so cp.async.wait_group(DP-1) is a
//          compile-time constant. Each lane copies and reads only its own
//          16B of the row -> no intra-warp sync needed.
// Last block (ticket) computes the scalar loss from the fp64 accumulators.
// ---------------------------------------------------------------------------
__global__ void __launch_bounds__(THREADS)
accum_kernel(const float* __restrict__ logits, float* __restrict__ out) {
    const int g      = blockIdx.y;            // segments [4g, 4g+3]
    const int warpId = threadIdx.x >> 5;
    const int lane   = threadIdx.x & 31;
    const int tid    = threadIdx.x;

    __shared__ unsigned short evbuf[EVCAP];               // 2 KB event list
    __shared__ int sCnt[WARPS];
    __shared__ float ring[WARPS][DP][2][NCOL];            // 24 KB stage ring

    // ---- Phase A: scan keys, count, prefix, write (loctok<<2 | sub) ----
    const unsigned* keys32 = (const unsigned*)g_keys;
    const int keyBase = (blockIdx.x * TOK_PER_BLOCK + warpId * TOK_PER_WARP) >> 2;
    unsigned w4[KITERS];
    #pragma unroll
    for (int it = 0; it < KITERS; ++it)
        w4[it] = __ldg(&keys32[keyBase + it * 32 + lane]);

    int cntW = 0;
    #pragma unroll
    for (int it = 0; it < KITERS; ++it) {
        #pragma unroll
        for (int k = 0; k < 4; ++k) {
            const int kb = (int)((w4[it] >> (8 * k)) & 0xFFu);
            cntW += __popc(__ballot_sync(0xFFFFFFFFu, (kb >> 2) == g));
        }
    }
    if (lane == 0) sCnt[warpId] = cntW;
    __syncthreads();
    int base = 0, Etot = 0;
    #pragma unroll
    for (int w = 0; w < WARPS; ++w) {
        if (w < warpId) base += sCnt[w];
        Etot += sCnt[w];
    }
    const unsigned lmask = (1u << lane) - 1u;
    #pragma unroll
    for (int it = 0; it < KITERS; ++it) {
        #pragma unroll
        for (int k = 0; k < 4; ++k) {
            const int kb = (int)((w4[it] >> (8 * k)) & 0xFFu);
            const bool match = (kb >> 2) == g;
            const unsigned m = __ballot_sync(0xFFFFFFFFu, match);
            if (match) {
                const int pos = base + __popc(m & lmask);
                const int loctok = warpId * TOK_PER_WARP + it * 128 + lane * 4 + k;
                if (pos < EVCAP)
                    evbuf[pos] = (unsigned short)((loctok << 2) | (kb & 3));
            }
            base += __popc(m);
        }
    }
    if (Etot > EVCAP) Etot = EVCAP;   // statistically unreachable (121 sigma)
    __syncthreads();

    // ---- Phase B: cp.async-staged, pair-per-group pipelined softmax ----
    float4 a0 = {0,0,0,0}, a1 = {0,0,0,0}, a2 = {0,0,0,0}, a3 = {0,0,0,0};
    float  ss0 = 0.f, ss1 = 0.f, ss2 = 0.f, ss3 = 0.f;
    int    c0 = 0, c1 = 0, c2 = 0, c3 = 0;

    const size_t rowBase = (size_t)blockIdx.x * TOK_PER_BLOCK;
    // events for this warp: global positions p = warpId + j*WARPS, j in [0,nE)
    const int nE = (Etot > warpId) ? ((Etot - warpId + WARPS - 1) / WARPS) : 0;
    const int nPairs = (nE + 1) >> 1;

    // issue one pair-group (possibly partial / empty); always commits.
    auto issue_pair = [&](int pi) {
        const int slot = pi % DP;
        const int jA = 2 * pi, jB = 2 * pi + 1;
        if (jA < nE) {
            const unsigned e = evbuf[warpId + jA * WARPS];
            const float* src = logits + (rowBase + (e >> 2)) * NCOL + lane * 4;
            const unsigned dst = (unsigned)__cvta_generic_to_shared(
                &ring[warpId][slot][0][lane * 4]);
            asm volatile("cp.async.cg.shared.global [%0], [%1], 16;"
                         :: "r"(dst), "l"(src) : "memory");
        }
        if (jB < nE) {
            const unsigned e = evbuf[warpId + jB * WARPS];
            const float* src = logits + (rowBase + (e >> 2)) * NCOL + lane * 4;
            const unsigned dst = (unsigned)__cvta_generic_to_shared(
                &ring[warpId][slot][1][lane * 4]);
            asm volatile("cp.async.cg.shared.global [%0], [%1], 16;"
                         :: "r"(dst), "l"(src) : "memory");
        }
        asm volatile("cp.async.commit_group;" ::: "memory");
    };

    #pragma unroll
    for (int pi = 0; pi < DP; ++pi) issue_pair(pi);   // prologue: DP pending

    for (int pi = 0; pi < nPairs; ++pi) {
        asm volatile("cp.async.wait_group %0;" :: "n"(DP - 1) : "memory");
        const int slot = pi % DP;
        const int jA = 2 * pi, jB = 2 * pi + 1;

        const unsigned eA = evbuf[warpId + jA * WARPS];
        const int uA = eA & 3;
        const float4 vA = *(const float4*)&ring[warpId][slot][0][lane * 4];
        int uB = -1; float4 vB = make_float4(0.f, 0.f, 0.f, 0.f);
        if (jB < nE) {
            uB = evbuf[warpId + jB * WARPS] & 3;
            vB = *(const float4*)&ring[warpId][slot][1][lane * 4];
        }

        issue_pair(pi + DP);   // refill this slot (DRAM latency >> LDS above)

        const float ea0 = __expf(vA.x), ea1 = __expf(vA.y);
        const float ea2 = __expf(vA.z), ea3 = __expf(vA.w);
        const float eb0 = __expf(vB.x), eb1 = __expf(vB.y);
        const float eb2 = __expf(vB.z), eb3 = __expf(vB.w);
        float sA = (ea0 + ea1) + (ea2 + ea3);
        float sB = (eb0 + eb1) + (eb2 + eb3);
        const float qA = ea0*ea0 + ea1*ea1 + ea2*ea2 + ea3*ea3;  // lane partials
        const float qB = eb0*eb0 + eb1*eb1 + eb2*eb2 + eb3*eb3;

        #pragma unroll
        for (int o = 16; o; o >>= 1) {         // two interleaved chains (ILP 2)
            sA += __shfl_xor_sync(0xFFFFFFFFu, sA, o);
            sB += __shfl_xor_sync(0xFFFFFFFFu, sB, o);
        }
        const float invA = __fdividef(1.0f, sA);
        const float invB = __fdividef(1.0f, sB);

        {   // event A (always valid inside loop)
            const float p0 = ea0*invA, p1 = ea1*invA, p2 = ea2*invA, p3 = ea3*invA;
            const float q  = qA * invA * invA;
            if (uA == 0)      { a0.x += p0; a0.y += p1; a0.z += p2; a0.w += p3; ss0 += q; c0++; }
            else if (uA == 1) { a1.x += p0; a1.y += p1; a1.z += p2; a1.w += p3; ss1 += q; c1++; }
            else if (uA == 2) { a2.x += p0; a2.y += p1; a2.z += p2; a2.w += p3; ss2 += q; c2++; }
            else              { a3.x += p0; a3.y += p1; a3.z += p2; a3.w += p3; ss3 += q; c3++; }
        }
        if (uB >= 0) {                         // warp-uniform guard
            const float p0 = eb0*invB, p1 = eb1*invB, p2 = eb2*invB, p3 = eb3*invB;
            const float q  = qB * invB * invB;
            if (uB == 0)      { a0.x += p0; a0.y += p1; a0.z += p2; a0.w += p3; ss0 += q; c0++; }
            else if (uB == 1) { a1.x += p0; a1.y += p1; a1.z += p2; a1.w += p3; ss1 += q; c1++; }
            else if (uB == 2) { a2.x += p0; a2.y += p1; a2.z += p2; a2.w += p3; ss2 += q; c2++; }
            else              { a3.x += p0; a3.y += p1; a3.z += p2; a3.w += p3; ss3 += q; c3++; }
        }
    }

    // warp-reduce ssq lane partials
    #pragma unroll
    for (int o = 16; o; o >>= 1) {
        ss0 += __shfl_xor_sync(0xFFFFFFFFu, ss0, o);
        ss1 += __shfl_xor_sync(0xFFFFFFFFu, ss1, o);
        ss2 += __shfl_xor_sync(0xFFFFFFFFu, ss2, o);
        ss3 += __shfl_xor_sync(0xFFFFFFFFu, ss3, o);
    }

    // block staging + cross-warp reduce; cross-block accumulation in fp64 atomics
    __shared__ float4 sh_s[WARPS][4][32];     // 16 KB
    __shared__ float  sh_ss[WARPS][4];
    __shared__ int    sh_cnt[WARPS][4];

    sh_s[warpId][0][lane] = a0;
    sh_s[warpId][1][lane] = a1;
    sh_s[warpId][2][lane] = a2;
    sh_s[warpId][3][lane] = a3;
    if (lane == 0) {
        sh_ss[warpId][0] = ss0; sh_ss[warpId][1] = ss1;
        sh_ss[warpId][2] = ss2; sh_ss[warpId][3] = ss3;
        sh_cnt[warpId][0] = c0; sh_cnt[warpId][1] = c1;
        sh_cnt[warpId][2] = c2; sh_cnt[warpId][3] = c3;
    }
    __syncthreads();

    const float* shf = (const float*)sh_s;    // [WARPS][512], idx = sub*128 + j
    #pragma unroll
    for (int e = tid; e < 512; e += THREADS) {
        double vsum = 0.0;
        #pragma unroll
        for (int w = 0; w < WARPS; ++w) vsum += (double)shf[w * 512 + e];
        const int sub2 = e >> 7, j = e & 127;
        atomicAdd(&g_s[(g * 4 + sub2) * NCOL + j], vsum);
    }
    if (tid < 4) {
        double vs = 0.0; int vc = 0;
        #pragma unroll
        for (int w = 0; w < WARPS; ++w) { vs += (double)sh_ss[w][tid]; vc += sh_cnt[w][tid]; }
        atomicAdd(&g_ssq[g * 4 + tid], vs);
        atomicAdd(&g_cnt[g * 4 + tid], vc);
    }

    // ---- fused finalize: last block to finish computes the scalar ----
    __threadfence();
    __syncthreads();
    __shared__ int sIsLast;
    if (tid == 0)
        sIsLast = (atomicAdd(&g_done, 1) == (int)(gridDim.x * gridDim.y) - 1);
    __syncthreads();
    if (!sIsLast) return;

    // 2 threads per segment row; .cg loads (accumulators live in L2)
    const int c    = tid >> 1;
    const int half = tid & 1;
    const double* row = g_s + c * NCOL + half * 64;
    double p0 = 0.0, p1 = 0.0;
    #pragma unroll
    for (int j = 0; j < 64; j += 2) {
        const double x = __ldcg(row + j), y = __ldcg(row + j + 1);
        p0 += x * x; p1 += y * y;
    }
    double s2 = p0 + p1;
    s2 += __shfl_xor_sync(0xFFFFFFFFu, s2, 1);

    __shared__ double sa[NCOL], sb[NCOL];
    if (half == 0) {
        const double n  = (double)__ldcg(g_cnt + c);
        const double ns = (n > 1.0) ? n : 1.0;
        const double colvar = (__ldcg(g_ssq + c) - s2 / ns) / (ns * (double)NCOL);
        sa[c] = (n > 1.0) ? colvar : 0.0;
        sb[c] = (n > 1.0) ? 1.0 : 0.0;
    }
    __syncthreads();
    for (int o = 64; o >= 1; o >>= 1) {
        if (tid < o) { sa[tid] += sa[tid + o]; sb[tid] += sb[tid + o]; }
        __syncthreads();
    }
    if (tid == 0) {
        const double cnt = (sb[0] > 1.0) ? sb[0] : 1.0;
        out[0] = (sb[0] > 0.0) ? (float)(sa[0] / cnt) : 0.0f;
    }
}

// ---------------------------------------------------------------------------
extern "C" void kernel_launch(void* const* d_in, const int* in_sizes, int n_in,
                              void* d_out, int out_size) {
    const float* logits = (const float*)d_in[0];
    const int*   assign = (const int*)d_in[1];
    const void*  mask   = d_in[2];

    init_pack_kernel<<<N_TOK / (THREADS * 4), THREADS>>>(assign, mask);
    accum_kernel<<<dim3(SPL, GROUPS), THREADS>>>(logits, (float*)d_out);
}

// round 15
// speedup vs baseline: 1.2094x; 1.2094x over previous
#include <cuda_runtime.h>
#include <stdint.h>

#define N_TOK (16 * 8192)   // 131072 tokens
#define NCOL 128            // C
#define GROUPS 32           // 4 segments per group
#define SPL 16              // accum token splits (8192 tokens per block)
#define SL32 32             // scatter slices (4096 tokens per slice)
#define THREADS 256
#define WARPS 8
#define CAP 256             // per-(slice32,group) bucket capacity (mean 64, 24 sigma)
#define EVS 512             // per-accum-block event capacity (mean 128, 34 sigma)
#define DP 3                // cp.async ring depth in PAIRS (6 rows in flight)

// Device scratch (no allocations allowed)
__device__ double   g_s[NCOL * NCOL];        // per-segment prob sums s[c][j]
__device__ double   g_ssq[NCOL];             // per-segment sum ||p||^2
__device__ int      g_cnt[NCOL];             // per-segment valid count n
__device__ int      g_bcnt[SL32 * GROUPS];   // bucket counters
__device__ unsigned g_ev[SL32 * GROUPS * CAP]; // bucket events: (tok<<2)|sub
__device__ int      g_done;                  // accum block-completion ticket

// ---------------------------------------------------------------------------
// Kernel 0: zero all accumulators/counters. 64 blocks x 256 threads.
// ---------------------------------------------------------------------------
__global__ void zero_kernel() {
    const int i = blockIdx.x * blockDim.x + threadIdx.x;
    if (i < NCOL * NCOL) g_s[i] = 0.0;
    if (i < NCOL) { g_ssq[i] = 0.0; g_cnt[i] = 0; }
    if (i < SL32 * GROUPS) g_bcnt[i] = 0;
    if (i == 0) g_done = 0;
}

// ---------------------------------------------------------------------------
// Kernel 1: scatter valid tokens into per-(slice32, group) GMEM buckets.
// 4 tokens/thread, vectorized. Replaces the old per-group ballot scan that
// every accum block repeated 32x (Phase A eliminated).
// Mask dtype detected per block from nonzero-byte pattern of first 4096 bytes.
// ---------------------------------------------------------------------------
__global__ void __launch_bounds__(THREADS)
scatter_kernel(const int* __restrict__ assign, const void* __restrict__ mask) {
    const int t = threadIdx.x;

    // --- inline mode detect (atomic-free, L2-hit broadcast) ---
    const uchar4* mb = (const uchar4*)mask;
    unsigned f = 0;
    #pragma unroll
    for (int k = 0; k < 4; ++k) {           // 256 thr * 4 uchar4 = 4096 bytes
        uchar4 u = mb[t * 4 + k];
        f |= (u.x ? 1u : 0u) | (u.y ? 2u : 0u) | (u.z ? 4u : 0u) | (u.w ? 8u : 0u);
    }
    f = __reduce_or_sync(0xFFFFFFFFu, f);
    __shared__ unsigned sf[WARPS];
    if ((t & 31) == 0) sf[t >> 5] = f;
    __syncthreads();
    unsigned fr = 0;
    #pragma unroll
    for (int w = 0; w < WARPS; ++w) fr |= sf[w];
    int mode;                                // 1=int32, 2=float32, 0=uint8
    if ((fr & 0xEu) == 0)      mode = 1;
    else if ((fr & 0x3u) == 0) mode = 2;
    else                       mode = 0;

    const int gid = blockIdx.x * blockDim.x + t;   // token-group id (4 tokens)
    if (gid * 4 >= N_TOK) return;

    const int4 a4 = __ldg((const int4*)assign + gid);
    int v[4];
    if (mode == 1) {
        const int4 m4 = __ldg((const int4*)mask + gid);
        v[0] = m4.x != 0; v[1] = m4.y != 0; v[2] = m4.z != 0; v[3] = m4.w != 0;
    } else if (mode == 2) {
        const float4 m4 = __ldg((const float4*)mask + gid);
        v[0] = m4.x != 0.f; v[1] = m4.y != 0.f; v[2] = m4.z != 0.f; v[3] = m4.w != 0.f;
    } else {
        const uchar4 m4 = ((const uchar4*)mask)[gid];
        v[0] = m4.x != 0; v[1] = m4.y != 0; v[2] = m4.z != 0; v[3] = m4.w != 0;
    }
    const int a[4] = {a4.x, a4.y, a4.z, a4.w};
    #pragma unroll
    for (int k = 0; k < 4; ++k) {
        if (v[k]) {
            const int tok   = gid * 4 + k;
            const int grp   = (a[k] >> 2) & 31;
            const int sub   = a[k] & 3;
            const int bkt   = (tok >> 12) * GROUPS + grp;   // slice32 * 32 + group
            const int pos   = atomicAdd(&g_bcnt[bkt], 1);
            if (pos < CAP)
                g_ev[bkt * CAP + pos] = ((unsigned)tok << 2) | (unsigned)sub;
        }
    }
}

// ---------------------------------------------------------------------------
// Kernel 2: accumulation + fused finalize. grid = (SPL, GROUPS).
// Reads its prebuilt event list (2 buckets) into smem, then the proven
// cp.async-staged 2-wide pipelined softmax (R14 Phase B, unchanged).
// Last block (ticket) computes the scalar loss from the fp64 accumulators.
// ---------------------------------------------------------------------------
__global__ void __launch_bounds__(THREADS)
accum_kernel(const float* __restrict__ logits, float* __restrict__ out) {
    const int g      = blockIdx.y;            // segments [4g, 4g+3]
    const int warpId = threadIdx.x >> 5;
    const int lane   = threadIdx.x & 31;
    const int tid    = threadIdx.x;

    __shared__ unsigned evbuf[EVS];                       // 2 KB event list
    __shared__ float ring[WARPS][DP][2][NCOL];            // 24 KB stage ring

    // ---- load this block's two buckets into smem (no scanning) ----
    const int b0 = (blockIdx.x * 2)     * GROUPS + g;
    const int b1 = (blockIdx.x * 2 + 1) * GROUPS + g;
    int c0 = __ldg(&g_bcnt[b0]); if (c0 > CAP) c0 = CAP;
    int c1 = __ldg(&g_bcnt[b1]); if (c1 > CAP) c1 = CAP;
    int Etot = c0 + c1; if (Etot > EVS) Etot = EVS;       // unreachable clamp
    for (int i = tid; i < c0; i += THREADS)
        evbuf[i] = __ldg(&g_ev[b0 * CAP + i]);
    for (int i = tid; i < Etot - c0; i += THREADS)
        evbuf[c0 + i] = __ldg(&g_ev[b1 * CAP + i]);
    __syncthreads();

    // ---- cp.async-staged, pair-per-group pipelined softmax ----
    float4 a0 = {0,0,0,0}, a1 = {0,0,0,0}, a2 = {0,0,0,0}, a3 = {0,0,0,0};
    float  ss0 = 0.f, ss1 = 0.f, ss2 = 0.f, ss3 = 0.f;
    int    c0s = 0, c1s = 0, c2s = 0, c3s = 0;

    // events for this warp: positions p = warpId + j*WARPS, j in [0,nE)
    const int nE = (Etot > warpId) ? ((Etot - warpId + WARPS - 1) / WARPS) : 0;
    const int nPairs = (nE + 1) >> 1;

    auto issue_pair = [&](int pi) {           // always commits (constant pending)
        const int slot = pi % DP;
        const int jA = 2 * pi, jB = 2 * pi + 1;
        if (jA < nE) {
            const unsigned e = evbuf[warpId + jA * WARPS];
            const float* src = logits + (size_t)(e >> 2) * NCOL + lane * 4;
            const unsigned dst = (unsigned)__cvta_generic_to_shared(
                &ring[warpId][slot][0][lane * 4]);
            asm volatile("cp.async.cg.shared.global [%0], [%1], 16;"
                         :: "r"(dst), "l"(src) : "memory");
        }
        if (jB < nE) {
            const unsigned e = evbuf[warpId + jB * WARPS];
            const float* src = logits + (size_t)(e >> 2) * NCOL + lane * 4;
            const unsigned dst = (unsigned)__cvta_generic_to_shared(
                &ring[warpId][slot][1][lane * 4]);
            asm volatile("cp.async.cg.shared.global [%0], [%1], 16;"
                         :: "r"(dst), "l"(src) : "memory");
        }
        asm volatile("cp.async.commit_group;" ::: "memory");
    };

    #pragma unroll
    for (int pi = 0; pi < DP; ++pi) issue_pair(pi);   // prologue: DP pending

    for (int pi = 0; pi < nPairs; ++pi) {
        asm volatile("cp.async.wait_group %0;" :: "n"(DP - 1) : "memory");
        const int slot = pi % DP;
        const int jA = 2 * pi, jB = 2 * pi + 1;

        const int uA = evbuf[warpId + jA * WARPS] & 3;
        const float4 vA = *(const float4*)&ring[warpId][slot][0][lane * 4];
        int uB = -1; float4 vB = make_float4(0.f, 0.f, 0.f, 0.f);
        if (jB < nE) {
            uB = evbuf[warpId + jB * WARPS] & 3;
            vB = *(const float4*)&ring[warpId][slot][1][lane * 4];
        }

        issue_pair(pi + DP);   // refill this slot

        const float ea0 = __expf(vA.x), ea1 = __expf(vA.y);
        const float ea2 = __expf(vA.z), ea3 = __expf(vA.w);
        const float eb0 = __expf(vB.x), eb1 = __expf(vB.y);
        const float eb2 = __expf(vB.z), eb3 = __expf(vB.w);
        float sA = (ea0 + ea1) + (ea2 + ea3);
        float sB = (eb0 + eb1) + (eb2 + eb3);
        const float qA = ea0*ea0 + ea1*ea1 + ea2*ea2 + ea3*ea3;  // lane partials
        const float qB = eb0*eb0 + eb1*eb1 + eb2*eb2 + eb3*eb3;

        #pragma unroll
        for (int o = 16; o; o >>= 1) {         // two interleaved chains (ILP 2)
            sA += __shfl_xor_sync(0xFFFFFFFFu, sA, o);
            sB += __shfl_xor_sync(0xFFFFFFFFu, sB, o);
        }
        const float invA = __fdividef(1.0f, sA);
        const float invB = __fdividef(1.0f, sB);

        {   // event A (always valid inside loop)
            const float p0 = ea0*invA, p1 = ea1*invA, p2 = ea2*invA, p3 = ea3*invA;
            const float q  = qA * invA * invA;
            if (uA == 0)      { a0.x += p0; a0.y += p1; a0.z += p2; a0.w += p3; ss0 += q; c0s++; }
            else if (uA == 1) { a1.x += p0; a1.y += p1; a1.z += p2; a1.w += p3; ss1 += q; c1s++; }
            else if (uA == 2) { a2.x += p0; a2.y += p1; a2.z += p2; a2.w += p3; ss2 += q; c2s++; }
            else              { a3.x += p0; a3.y += p1; a3.z += p2; a3.w += p3; ss3 += q; c3s++; }
        }
        if (uB >= 0) {                         // warp-uniform guard
            const float p0 = eb0*invB, p1 = eb1*invB, p2 = eb2*invB, p3 = eb3*invB;
            const float q  = qB * invB * invB;
            if (uB == 0)      { a0.x += p0; a0.y += p1; a0.z += p2; a0.w += p3; ss0 += q; c0s++; }
            else if (uB == 1) { a1.x += p0; a1.y += p1; a1.z += p2; a1.w += p3; ss1 += q; c1s++; }
            else if (uB == 2) { a2.x += p0; a2.y += p1; a2.z += p2; a2.w += p3; ss2 += q; c2s++; }
            else              { a3.x += p0; a3.y += p1; a3.z += p2; a3.w += p3; ss3 += q; c3s++; }
        }
    }

    // warp-reduce ssq lane partials
    #pragma unroll
    for (int o = 16; o; o >>= 1) {
        ss0 += __shfl_xor_sync(0xFFFFFFFFu, ss0, o);
        ss1 += __shfl_xor_sync(0xFFFFFFFFu, ss1, o);
        ss2 += __shfl_xor_sync(0xFFFFFFFFu, ss2, o);
        ss3 += __shfl_xor_sync(0xFFFFFFFFu, ss3, o);
    }

    // block staging + cross-warp reduce; cross-block accumulation in fp64 atomics
    __shared__ float4 sh_s[WARPS][4][32];     // 16 KB
    __shared__ float  sh_ss[WARPS][4];
    __shared__ int    sh_cnt[WARPS][4];

    sh_s[warpId][0][lane] = a0;
    sh_s[warpId][1][lane] = a1;
    sh_s[warpId][2][lane] = a2;
    sh_s[warpId][3][lane] = a3;
    if (lane == 0) {
        sh_ss[warpId][0] = ss0; sh_ss[warpId][1] = ss1;
        sh_ss[warpId][2] = ss2; sh_ss[warpId][3] = ss3;
        sh_cnt[warpId][0] = c0s; sh_cnt[warpId][1] = c1s;
        sh_cnt[warpId][2] = c2s; sh_cnt[warpId][3] = c3s;
    }
    __syncthreads();

    const float* shf = (const float*)sh_s;    // [WARPS][512], idx = sub*128 + j
    #pragma unroll
    for (int e = tid; e < 512; e += THREADS) {
        double vsum = 0.0;
        #pragma unroll
        for (int w = 0; w < WARPS; ++w) vsum += (double)shf[w * 512 + e];
        const int sub2 = e >> 7, j = e & 127;
        atomicAdd(&g_s[(g * 4 + sub2) * NCOL + j], vsum);
    }
    if (tid < 4) {
        double vs = 0.0; int vc = 0;
        #pragma unroll
        for (int w = 0; w < WARPS; ++w) { vs += (double)sh_ss[w][tid]; vc += sh_cnt[w][tid]; }
        atomicAdd(&g_ssq[g * 4 + tid], vs);
        atomicAdd(&g_cnt[g * 4 + tid], vc);
    }

    // ---- fused finalize: last block to finish computes the scalar ----
    __threadfence();
    __syncthreads();
    __shared__ int sIsLast;
    if (tid == 0)
        sIsLast = (atomicAdd(&g_done, 1) == (int)(gridDim.x * gridDim.y) - 1);
    __syncthreads();
    if (!sIsLast) return;

    // 2 threads per segment row; .cg loads (accumulators live in L2)
    const int c    = tid >> 1;
    const int half = tid & 1;
    const double* row = g_s + c * NCOL + half * 64;
    double p0 = 0.0, p1 = 0.0;
    #pragma unroll
    for (int j = 0; j < 64; j += 2) {
        const double x = __ldcg(row + j), y = __ldcg(row + j + 1);
        p0 += x * x; p1 += y * y;
    }
    double s2 = p0 + p1;
    s2 += __shfl_xor_sync(0xFFFFFFFFu, s2, 1);

    __shared__ double sa[NCOL], sb[NCOL];
    if (half == 0) {
        const double n  = (double)__ldcg(g_cnt + c);
        const double ns = (n > 1.0) ? n : 1.0;
        const double colvar = (__ldcg(g_ssq + c) - s2 / ns) / (ns * (double)NCOL);
        sa[c] = (n > 1.0) ? colvar : 0.0;
        sb[c] = (n > 1.0) ? 1.0 : 0.0;
    }
    __syncthreads();
    for (int o = 64; o >= 1; o >>= 1) {
        if (tid < o) { sa[tid] += sa[tid + o]; sb[tid] += sb[tid + o]; }
        __syncthreads();
    }
    if (tid == 0) {
        const double cnt = (sb[0] > 1.0) ? sb[0] : 1.0;
        out[0] = (sb[0] > 0.0) ? (float)(sa[0] / cnt) : 0.0f;
    }
}

// ---------------------------------------------------------------------------
extern "C" void kernel_launch(void* const* d_in, const int* in_sizes, int n_in,
                              void* d_out, int out_size) {
    const float* logits = (const float*)d_in[0];
    const int*   assign = (const int*)d_in[1];
    const void*  mask   = d_in[2];

    zero_kernel<<<(NCOL * NCOL + THREADS - 1) / THREADS, THREADS>>>();
    scatter_kernel<<<N_TOK / (THREADS * 4), THREADS>>>(assign, mask);
    accum_kernel<<<dim3(SPL, GROUPS), THREADS>>>(logits, (float*)d_out);
}